// round 1
// baseline (speedup 1.0000x reference)
#include <cuda_runtime.h>
#include <math.h>

// Problem dims (fixed by reference: B=1024, L=256)
#define NRES 262144
#define NBLK 1024
#define TPB  256
#define BLEN 1.52f
#define PI_F 3.14159265358979323846f

// ---------------- small vec helpers ----------------
struct V3 { float x, y, z; };
__device__ __forceinline__ V3 v3(float a, float b, float c) { V3 r; r.x = a; r.y = b; r.z = c; return r; }
__device__ __forceinline__ V3 operator+(V3 a, V3 b) { return v3(a.x + b.x, a.y + b.y, a.z + b.z); }
__device__ __forceinline__ V3 operator-(V3 a, V3 b) { return v3(a.x - b.x, a.y - b.y, a.z - b.z); }
__device__ __forceinline__ V3 operator*(V3 a, float s) { return v3(a.x * s, a.y * s, a.z * s); }
__device__ __forceinline__ float dot3(V3 a, V3 b) { return a.x * b.x + a.y * b.y + a.z * b.z; }
__device__ __forceinline__ V3 crs3(V3 a, V3 b) {
    return v3(a.y * b.z - a.z * b.y, a.z * b.x - a.x * b.z, a.x * b.y - a.y * b.x);
}

// ---------------- residue-type tables ----------------
__constant__ int c_nsc[21]  = {1,7,4,4,2,5,5,0,6,4,4,5,4,7,3,2,3,10,8,3,0};
__constant__ int c_chin[21] = {0,4,2,2,1,3,3,0,2,2,2,4,3,2,2,1,1,2,2,1,0};

// ---------------- device state (static; no runtime alloc) ----------------
__device__ float  d_chi[4 * NRES];
__device__ float  d_m  [4 * NRES];
__device__ float  d_v  [4 * NRES];
__device__ float  d_g  [4 * NRES];
__device__ float  d_pre[15 * NRES];   // SoA: p1(0..2), CB(3..5), bc1(6..8), n1(9..11), m1(12..14)
__device__ float  d_tgt[30 * NRES];   // SoA transposed sidechain targets
__device__ int    d_nsc[NRES];
__device__ double d_part[NBLK];
__device__ float  d_mse_prev;
__device__ int    d_done, d_t, d_cnt;
__device__ float  d_invden, d_bc1m, d_bc2v;

__device__ __forceinline__ V3 ldpre(int c, int i) {
    return v3(d_pre[(3 * c + 0) * NRES + i], d_pre[(3 * c + 1) * NRES + i], d_pre[(3 * c + 2) * NRES + i]);
}
__device__ __forceinline__ void stpre(int c, int i, V3 a) {
    d_pre[(3 * c + 0) * NRES + i] = a.x;
    d_pre[(3 * c + 1) * NRES + i] = a.y;
    d_pre[(3 * c + 2) * NRES + i] = a.z;
}
__device__ __forceinline__ V3 ldtgt(int s, int i) {
    return v3(d_tgt[(3 * s + 0) * NRES + i], d_tgt[(3 * s + 1) * NRES + i], d_tgt[(3 * s + 2) * NRES + i]);
}

// NeRF extend, primal only
__device__ __forceinline__ V3 extendp(V3 a, V3 b, V3 c, float cT, float sT) {
    const float cA = cosf(1.937f), sA = sinf(1.937f);
    V3 v = c - b; float nv = sqrtf(dot3(v, v)); V3 u = v * (1.f / (nv + 1e-8f));
    V3 w = b - a; V3 pp = crs3(w, u); float np = sqrtf(dot3(pp, pp)); V3 nn = pp * (1.f / (np + 1e-8f));
    V3 mm = crs3(nn, u);
    return c + (u * (-cA) + (mm * cT + nn * sT) * sA) * BLEN;
}

__device__ __forceinline__ float dihed(V3 a, V3 b, V3 c, V3 d) {
    V3 b1 = b - a, b2 = c - b, b3 = d - c;
    V3 n1 = crs3(b1, b2), n2 = crs3(b2, b3);
    float nb = sqrtf(dot3(b2, b2));
    V3 u2 = b2 * (1.f / (nb + 1e-8f));
    V3 m1 = crs3(n1, u2);
    return atan2f(dot3(m1, n2), dot3(n1, n2));
}

// ---------------- kernels ----------------
__global__ void k_init() {
    d_done = 0; d_t = 0; d_mse_prev = 100.0f; d_cnt = 0;
    d_bc1m = 1.0f - powf(0.9f, 1.0f);
    d_bc2v = 1.0f - powf(0.999f, 1.0f);
}

__global__ void k_pre(const float* __restrict__ X, const int* __restrict__ S) {
    int i = blockIdx.x * TPB + threadIdx.x;
    const float* xr = X + (size_t)i * 42;
    V3 p[9];
#pragma unroll
    for (int j = 0; j < 9; j++) p[j] = v3(xr[3 * j], xr[3 * j + 1], xr[3 * j + 2]);

    int s20 = S[i] % 21;
    int nsc = c_nsc[s20], chin = c_chin[s20];
    d_nsc[i] = nsc;
    atomicAdd(&d_cnt, nsc);

    // chi0 = masked dihedrals over quads (0,1,4,5),(1,4,5,6),(4,5,6,7),(5,6,7,8)
    const int Q[4][4] = {{0,1,4,5},{1,4,5,6},{4,5,6,7},{5,6,7,8}};
#pragma unroll
    for (int k = 0; k < 4; k++) {
        float ch = 0.f;
        if (k < chin) ch = dihed(p[Q[k][0]], p[Q[k][1]], p[Q[k][2]], p[Q[k][3]]);
        d_chi[k * NRES + i] = ch;
        d_m[k * NRES + i] = 0.f;
        d_v[k * NRES + i] = 0.f;
    }

    // CB (slot 0): parents (0,2,1), fixed torsion
    V3 cb = extendp(p[0], p[2], p[1], cosf(-2.14f), sinf(-2.14f));
    // Constant frame for slot 1: parents (0,1,CB)
    V3 vv = cb - p[1]; float nv = sqrtf(dot3(vv, vv)); V3 u = vv * (1.f / (nv + 1e-8f));
    V3 w = p[1] - p[0]; V3 pp = crs3(w, u); float np = sqrtf(dot3(pp, pp)); V3 nn = pp * (1.f / (np + 1e-8f));
    V3 mm = crs3(nn, u);
    stpre(0, i, p[1]); stpre(1, i, cb); stpre(2, i, u); stpre(3, i, nn); stpre(4, i, mm);

    // transpose targets to SoA
#pragma unroll
    for (int s = 0; s < 10; s++) {
#pragma unroll
        for (int j = 0; j < 3; j++) d_tgt[(3 * s + j) * NRES + i] = xr[(4 + s) * 3 + j];
    }
}

__global__ void k_invden() { d_invden = 1.0f / (3.0f * (float)d_cnt); }

// One optimization iteration: optional Adam step (using previous gradient),
// then forward rebuild + forward-mode JVP (4 tangents) -> new gradient + loss partials.
__global__ void k_iter(int is_step) {
    if (d_done) return;
    int i = blockIdx.x * TPB + threadIdx.x;
    const float cA = cosf(1.937f), sA = sinf(1.937f);

    float chi[4];
    if (is_step) {
        float b1c = d_bc1m, b2c = d_bc2v;
#pragma unroll
        for (int k = 0; k < 4; k++) {
            float g = d_g[k * NRES + i];
            float m = 0.9f * d_m[k * NRES + i] + 0.1f * g;
            float v = 0.999f * d_v[k * NRES + i] + 0.001f * g * g;
            d_m[k * NRES + i] = m;
            d_v[k * NRES + i] = v;
            float mh = m / b1c, vh = v / b2c;
            float c = d_chi[k * NRES + i] - mh / (sqrtf(vh) + 1e-8f);
            d_chi[k * NRES + i] = c;
            chi[k] = c;
        }
    } else {
#pragma unroll
        for (int k = 0; k < 4; k++) chi[k] = d_chi[k * NRES + i];
    }

    int nsc = d_nsc[i];
    V3 p1 = ldpre(0, i), cb = ldpre(1, i), u1 = ldpre(2, i), n1 = ldpre(3, i), m1 = ldpre(4, i);

    float loss = 0.f;
    float gacc[4] = {0.f, 0.f, 0.f, 0.f};

    // slot 0 (CB): chi-independent, loss only
    if (nsc > 0) { V3 df = cb - ldtgt(0, i); loss += dot3(df, df); }

    // slot 1: constant frame, torsion = chi0
    float c0 = cosf(chi[0]), s0 = sinf(chi[0]);
    V3 A5 = cb + (u1 * (-cA) + (m1 * c0 + n1 * s0) * sA) * BLEN;
    V3 t5 = (n1 * c0 - m1 * s0) * (sA * BLEN);   // dA5/dchi0
    if (nsc > 1) { V3 df = A5 - ldtgt(1, i); loss += dot3(df, df); gacc[0] += 2.f * dot3(df, t5); }

    // rolling chain state + 4 tangents per atom
    V3 a = p1, b = cb, c = A5;
    V3 at[4], bt[4], ct[4];
#pragma unroll
    for (int k = 0; k < 4; k++) { at[k] = v3(0, 0, 0); bt[k] = v3(0, 0, 0); ct[k] = v3(0, 0, 0); }
    ct[0] = t5;

#pragma unroll
    for (int s = 2; s < 10; s++) {
        float cT, sT; int ka;
        if (s <= 4) { float T = chi[s - 1]; cT = cosf(T); sT = sinf(T); ka = s - 1; }
        else        { cT = cosf(PI_F); sT = sinf(PI_F); ka = -1; }

        V3 v = c - b; float nv = sqrtf(dot3(v, v)); float iv = 1.f / (nv + 1e-8f);
        V3 u = v * iv;
        V3 w = b - a;
        V3 pp = crs3(w, u); float np = sqrtf(dot3(pp, pp)); float ip = 1.f / (np + 1e-8f);
        V3 nn = pp * ip;
        V3 mm = crs3(nn, u);
        V3 d = c + (u * (-cA) + (mm * cT + nn * sT) * sA) * BLEN;

        V3 dt[4];
#pragma unroll
        for (int k = 0; k < 4; k++) {
            V3 vd = ct[k] - bt[k];
            float nvd = dot3(v, vd) / nv;
            V3 ud = vd * iv - v * (nvd * iv * iv);
            V3 wd = bt[k] - at[k];
            V3 pd = crs3(wd, u) + crs3(w, ud);
            float npd = dot3(pp, pd) / np;
            V3 nd = pd * ip - pp * (npd * ip * ip);
            V3 md = crs3(nd, u) + crs3(nn, ud);
            V3 dd = ct[k] + (ud * (-cA) + (md * cT + nd * sT) * sA) * BLEN;
            if (k == ka) dd = dd + (nn * cT - mm * sT) * (sA * BLEN);
            dt[k] = dd;
        }

        if (s < nsc) {
            V3 df = d - ldtgt(s, i);
            loss += dot3(df, df);
#pragma unroll
            for (int k = 0; k < 4; k++) gacc[k] += 2.f * dot3(df, dt[k]);
        }
        a = b; b = c; c = d;
#pragma unroll
        for (int k = 0; k < 4; k++) { at[k] = bt[k]; bt[k] = ct[k]; ct[k] = dt[k]; }
    }

    float ivd = d_invden;
#pragma unroll
    for (int k = 0; k < 4; k++) d_g[k * NRES + i] = gacc[k] * ivd;

    // deterministic fixed-order block reduction (double)
    __shared__ double sh[TPB];
    sh[threadIdx.x] = (double)loss;
    __syncthreads();
    for (int o = TPB / 2; o > 0; o >>= 1) {
        if (threadIdx.x < o) sh[threadIdx.x] += sh[threadIdx.x + o];
        __syncthreads();
    }
    if (threadIdx.x == 0) d_part[blockIdx.x] = sh[0];
}

__global__ void k_red(int first) {
    if (d_done) return;
    __shared__ double sh[TPB];
    int t = threadIdx.x;
    double s = 0.0;
    for (int j = t; j < NBLK; j += TPB) s += d_part[j];   // fixed order -> deterministic
    sh[t] = s; __syncthreads();
    for (int o = TPB / 2; o > 0; o >>= 1) {
        if (t < o) sh[t] += sh[t + o];
        __syncthreads();
    }
    if (t == 0) {
        float mse = (float)(sh[0] / (3.0 * (double)d_cnt));
        if (first) {
            if (fabsf(mse - 100.0f) < 1e-4f) d_done = 1;
        } else {
            if (fabsf(mse - d_mse_prev) < 1e-4f) d_done = 1;
            int t1 = d_t + 1; d_t = t1;
            if (t1 >= 200) d_done = 1;
        }
        d_mse_prev = mse;
        // bias corrections for the NEXT Adam step (f32 like reference)
        float tf = (float)(d_t + 1);
        d_bc1m = 1.0f - powf(0.9f, tf);
        d_bc2v = 1.0f - powf(0.999f, tf);
    }
}

__global__ void k_final(const float* __restrict__ X, float* __restrict__ out) {
    int i = blockIdx.x * TPB + threadIdx.x;
    const float cA = cosf(1.937f), sA = sinf(1.937f);
    const float* xr = X + (size_t)i * 42;
    float* o = out + (size_t)i * 42;
#pragma unroll
    for (int j = 0; j < 12; j++) o[j] = xr[j];   // backbone passthrough

    float chi[4];
#pragma unroll
    for (int k = 0; k < 4; k++) chi[k] = d_chi[k * NRES + i];

    V3 p1 = ldpre(0, i), cb = ldpre(1, i), u1 = ldpre(2, i), n1 = ldpre(3, i), m1 = ldpre(4, i);
    V3 atoms[10];
    atoms[0] = cb;
    float c0 = cosf(chi[0]), s0 = sinf(chi[0]);
    V3 A5 = cb + (u1 * (-cA) + (m1 * c0 + n1 * s0) * sA) * BLEN;
    atoms[1] = A5;
    V3 a = p1, b = cb, c = A5;
#pragma unroll
    for (int s = 2; s < 10; s++) {
        float cT, sT;
        if (s <= 4) { float T = chi[s - 1]; cT = cosf(T); sT = sinf(T); }
        else        { cT = cosf(PI_F); sT = sinf(PI_F); }
        V3 d = extendp(a, b, c, cT, sT);
        atoms[s] = d;
        a = b; b = c; c = d;
    }
#pragma unroll
    for (int s = 0; s < 10; s++) {
        o[12 + 3 * s] = atoms[s].x;
        o[13 + 3 * s] = atoms[s].y;
        o[14 + 3 * s] = atoms[s].z;
    }
}

// ---------------- launch ----------------
extern "C" void kernel_launch(void* const* d_in, const int* in_sizes, int n_in,
                              void* d_out, int out_size) {
    const float* X = (const float*)d_in[0];
    const int*   S = (const int*)d_in[1];
    // d_in[2] = batch_ids: contiguous equal segments -> pure reshape, unused.
    float* out = (float*)d_out;

    k_init<<<1, 1>>>();
    k_pre<<<NBLK, TPB>>>(X, S);
    k_invden<<<1, 1>>>();

    // initial loss/gradient at chi0 (no Adam step)
    k_iter<<<NBLK, TPB>>>(0);
    k_red<<<1, TPB>>>(1);

    // up to 200 Adam steps, device-side convergence gating
    for (int it = 0; it < 200; ++it) {
        k_iter<<<NBLK, TPB>>>(1);
        k_red<<<1, TPB>>>(0);
    }

    k_final<<<NBLK, TPB>>>(X, out);
}

// round 2
// speedup vs baseline: 1.8009x; 1.8009x over previous
#include <cuda_runtime.h>
#include <math.h>

// Problem dims (fixed by reference: B=1024, L=256)
#define NRES 262144
#define TPB  256
#define NBLK (NRES / TPB)
#define BLEN 1.52f
#define PI_F 3.14159265358979323846f

// ---------------- small vec helpers ----------------
struct V3 { float x, y, z; };
__device__ __forceinline__ V3 v3(float a, float b, float c) { V3 r; r.x = a; r.y = b; r.z = c; return r; }
__device__ __forceinline__ V3 operator+(V3 a, V3 b) { return v3(a.x + b.x, a.y + b.y, a.z + b.z); }
__device__ __forceinline__ V3 operator-(V3 a, V3 b) { return v3(a.x - b.x, a.y - b.y, a.z - b.z); }
__device__ __forceinline__ V3 operator*(V3 a, float s) { return v3(a.x * s, a.y * s, a.z * s); }
__device__ __forceinline__ float dot3(V3 a, V3 b) { return a.x * b.x + a.y * b.y + a.z * b.z; }
__device__ __forceinline__ V3 crs3(V3 a, V3 b) {
    return v3(a.y * b.z - a.z * b.y, a.z * b.x - a.x * b.z, a.x * b.y - a.y * b.x);
}

// ---------------- residue-type tables ----------------
__constant__ int c_nsc[21]  = {1,7,4,4,2,5,5,0,6,4,4,5,4,7,3,2,3,10,8,3,0};
__constant__ int c_chin[21] = {0,4,2,2,1,3,3,0,2,2,2,4,3,2,2,1,1,2,2,1,0};

// ---------------- device state (static; no runtime alloc) ----------------
// All per-residue arrays below are indexed by SORTED position j (sorted by n_sc).
__device__ float  d_chi[4 * NRES];
__device__ float  d_m  [4 * NRES];
__device__ float  d_v  [4 * NRES];
__device__ float  d_g  [4 * NRES];
__device__ float  d_pre[15 * NRES];   // SoA: p1, CB, u1, n1, m1
__device__ float  d_tgt[30 * NRES];   // SoA transposed sidechain targets
__device__ int    d_nsc[NRES];        // n_sc at sorted position
__device__ int    d_inv[NRES];        // original residue i -> sorted position j
__device__ int    d_bhist[11 * NBLK]; // counting-sort block histograms / offsets
__device__ double d_part[NBLK];
__device__ float  d_mse_prev;
__device__ int    d_done, d_t, d_cnt, d_ticket;
__device__ float  d_invden, d_bc1m, d_bc2v;

__device__ __forceinline__ V3 ldpre(int c, int j) {
    return v3(d_pre[(3 * c + 0) * NRES + j], d_pre[(3 * c + 1) * NRES + j], d_pre[(3 * c + 2) * NRES + j]);
}
__device__ __forceinline__ void stpre(int c, int j, V3 a) {
    d_pre[(3 * c + 0) * NRES + j] = a.x;
    d_pre[(3 * c + 1) * NRES + j] = a.y;
    d_pre[(3 * c + 2) * NRES + j] = a.z;
}
__device__ __forceinline__ V3 ldtgt(int s, int j) {
    return v3(d_tgt[(3 * s + 0) * NRES + j], d_tgt[(3 * s + 1) * NRES + j], d_tgt[(3 * s + 2) * NRES + j]);
}

// NeRF extend, primal only
__device__ __forceinline__ V3 extendp(V3 a, V3 b, V3 c, float cT, float sT) {
    const float cA = cosf(1.937f), sA = sinf(1.937f);
    V3 v = c - b; float nv = sqrtf(dot3(v, v)); V3 u = v * (1.f / (nv + 1e-8f));
    V3 w = b - a; V3 pp = crs3(w, u); float np = sqrtf(dot3(pp, pp)); V3 nn = pp * (1.f / (np + 1e-8f));
    V3 mm = crs3(nn, u);
    return c + (u * (-cA) + (mm * cT + nn * sT) * sA) * BLEN;
}

__device__ __forceinline__ float dihed(V3 a, V3 b, V3 c, V3 d) {
    V3 b1 = b - a, b2 = c - b, b3 = d - c;
    V3 n1 = crs3(b1, b2), n2 = crs3(b2, b3);
    float nb = sqrtf(dot3(b2, b2));
    V3 u2 = b2 * (1.f / (nb + 1e-8f));
    V3 m1 = crs3(n1, u2);
    return atan2f(dot3(m1, n2), dot3(n1, n2));
}

// ---------------- counting sort by n_sc (deterministic / stable) ----------------
__global__ void k_hist(const int* __restrict__ S) {
    __shared__ int h[11];
    int tid = threadIdx.x;
    if (tid < 11) h[tid] = 0;
    __syncthreads();
    int i = blockIdx.x * TPB + tid;
    int nsc = c_nsc[S[i] % 21];
    atomicAdd(&h[nsc], 1);
    __syncthreads();
    if (tid < 11) d_bhist[tid * NBLK + blockIdx.x] = h[tid];
}

__global__ void k_scan() {
    int v = threadIdx.x;
    __shared__ int tot[11], base[11];
    if (v < 11) {
        int s = 0;
        for (int b = 0; b < NBLK; b++) s += d_bhist[v * NBLK + b];
        tot[v] = s;
    }
    __syncthreads();
    if (v == 0) {
        int o = 0, cnt = 0;
        for (int u = 0; u < 11; u++) { base[u] = o; o += tot[u]; cnt += u * tot[u]; }
        d_cnt = cnt;
        d_invden = 1.0f / (3.0f * (float)cnt);
        d_done = 0; d_t = 0; d_mse_prev = 100.0f; d_ticket = 0;
        d_bc1m = 1.0f - powf(0.9f, 1.0f);
        d_bc2v = 1.0f - powf(0.999f, 1.0f);
    }
    __syncthreads();
    if (v < 11) {
        int off = base[v];
        for (int b = 0; b < NBLK; b++) {
            int t = d_bhist[v * NBLK + b];
            d_bhist[v * NBLK + b] = off;
            off += t;
        }
    }
}

// scatter + per-residue precompute, stored at sorted position j
__global__ void k_scatter(const float* __restrict__ X, const int* __restrict__ S) {
    int tid = threadIdx.x;
    int i = blockIdx.x * TPB + tid;
    int w = tid >> 5, lane = tid & 31;

    int s20 = S[i] % 21;
    int nsc = c_nsc[s20], chin = c_chin[s20];

    __shared__ int whist[8][11];
    if (tid < 88) ((int*)whist)[tid] = 0;
    __syncthreads();
    unsigned mmask = __match_any_sync(0xffffffffu, nsc);
    int rank = __popc(mmask & ((1u << lane) - 1u));
    if (rank == 0) whist[w][nsc] = __popc(mmask);
    __syncthreads();
    int wb = 0;
    for (int w2 = 0; w2 < w; w2++) wb += whist[w2][nsc];
    int j = d_bhist[nsc * NBLK + blockIdx.x] + wb + rank;

    d_inv[i] = j;
    d_nsc[j] = nsc;

    const float* xr = X + (size_t)i * 42;
    V3 p[9];
#pragma unroll
    for (int q = 0; q < 9; q++) p[q] = v3(xr[3 * q], xr[3 * q + 1], xr[3 * q + 2]);

    // chi0 = masked dihedrals over quads
    const int Q[4][4] = {{0,1,4,5},{1,4,5,6},{4,5,6,7},{5,6,7,8}};
#pragma unroll
    for (int k = 0; k < 4; k++) {
        float ch = 0.f;
        if (k < chin) ch = dihed(p[Q[k][0]], p[Q[k][1]], p[Q[k][2]], p[Q[k][3]]);
        d_chi[k * NRES + j] = ch;
        d_m[k * NRES + j] = 0.f;
        d_v[k * NRES + j] = 0.f;
    }

    // CB (slot 0): parents (0,2,1), fixed torsion
    V3 cb = extendp(p[0], p[2], p[1], cosf(-2.14f), sinf(-2.14f));
    // Constant frame for slot 1: parents (0,1,CB)
    V3 vv = cb - p[1]; float nv = sqrtf(dot3(vv, vv)); V3 u = vv * (1.f / (nv + 1e-8f));
    V3 ww = p[1] - p[0]; V3 pp = crs3(ww, u); float np = sqrtf(dot3(pp, pp)); V3 nn = pp * (1.f / (np + 1e-8f));
    V3 mm = crs3(nn, u);
    stpre(0, j, p[1]); stpre(1, j, cb); stpre(2, j, u); stpre(3, j, nn); stpre(4, j, mm);

#pragma unroll
    for (int s = 0; s < 10; s++) {
#pragma unroll
        for (int q = 0; q < 3; q++) d_tgt[(3 * s + q) * NRES + j] = xr[(4 + s) * 3 + q];
    }
}

// One optimization iteration with fused last-block MSE reduction.
__global__ void __launch_bounds__(TPB, 3) k_iter(int is_step, int first) {
    if (d_done) return;
    int tid = threadIdx.x;
    int j = blockIdx.x * TPB + tid;
    const float cA = cosf(1.937f), sA = sinf(1.937f);

    float chi[4];
    if (is_step) {
        float b1c = d_bc1m, b2c = d_bc2v;
#pragma unroll
        for (int k = 0; k < 4; k++) {
            float g = d_g[k * NRES + j];
            float m = 0.9f * d_m[k * NRES + j] + 0.1f * g;
            float v = 0.999f * d_v[k * NRES + j] + 0.001f * g * g;
            d_m[k * NRES + j] = m;
            d_v[k * NRES + j] = v;
            float mh = m / b1c, vh = v / b2c;
            float c = d_chi[k * NRES + j] - mh / (sqrtf(vh) + 1e-8f);
            d_chi[k * NRES + j] = c;
            chi[k] = c;
        }
    } else {
#pragma unroll
        for (int k = 0; k < 4; k++) chi[k] = d_chi[k * NRES + j];
    }

    int nsc = d_nsc[j];
    unsigned nscmax = __reduce_max_sync(0xffffffffu, (unsigned)nsc);

    float loss = 0.f;
    float gacc[4] = {0.f, 0.f, 0.f, 0.f};

    if (nscmax > 0) {
        V3 cb = ldpre(1, j);
        if (nsc > 0) { V3 df = cb - ldtgt(0, j); loss += dot3(df, df); }

        if (nscmax > 1) {
            V3 p1 = ldpre(0, j), u1 = ldpre(2, j), n1 = ldpre(3, j), m1 = ldpre(4, j);
            float c0 = cosf(chi[0]), s0 = sinf(chi[0]);
            V3 A5 = cb + (u1 * (-cA) + (m1 * c0 + n1 * s0) * sA) * BLEN;
            V3 t5 = (n1 * c0 - m1 * s0) * (sA * BLEN);
            if (nsc > 1) { V3 df = A5 - ldtgt(1, j); loss += dot3(df, df); gacc[0] += 2.f * dot3(df, t5); }

            V3 a = p1, b = cb, c = A5;
            V3 at[4], bt[4], ct[4];
#pragma unroll
            for (int k = 0; k < 4; k++) { at[k] = v3(0,0,0); bt[k] = v3(0,0,0); ct[k] = v3(0,0,0); }
            ct[0] = t5;

#pragma unroll
            for (int s = 2; s < 10; s++) {
                if ((unsigned)s >= nscmax) break;   // warp-uniform after sort
                float cT, sT; int ka;
                if (s <= 4) { float T = chi[s - 1]; cT = cosf(T); sT = sinf(T); ka = s - 1; }
                else        { cT = cosf(PI_F); sT = sinf(PI_F); ka = -1; }

                V3 v = c - b; float nv = sqrtf(dot3(v, v)); float iv = 1.f / (nv + 1e-8f);
                V3 u = v * iv;
                V3 w = b - a;
                V3 pp = crs3(w, u); float np = sqrtf(dot3(pp, pp)); float ip = 1.f / (np + 1e-8f);
                V3 nn = pp * ip;
                V3 mm = crs3(nn, u);
                V3 d = c + (u * (-cA) + (mm * cT + nn * sT) * sA) * BLEN;

                V3 dt[4];
#pragma unroll
                for (int k = 0; k < 4; k++) {
                    V3 vd = ct[k] - bt[k];
                    float nvd = dot3(v, vd) / nv;
                    V3 ud = vd * iv - v * (nvd * iv * iv);
                    V3 wd = bt[k] - at[k];
                    V3 pd = crs3(wd, u) + crs3(w, ud);
                    float npd = dot3(pp, pd) / np;
                    V3 nd = pd * ip - pp * (npd * ip * ip);
                    V3 md = crs3(nd, u) + crs3(nn, ud);
                    V3 dd = ct[k] + (ud * (-cA) + (md * cT + nd * sT) * sA) * BLEN;
                    if (k == ka) dd = dd + (nn * cT - mm * sT) * (sA * BLEN);
                    dt[k] = dd;
                }

                if (s < nsc) {
                    V3 df = d - ldtgt(s, j);
                    loss += dot3(df, df);
#pragma unroll
                    for (int k = 0; k < 4; k++) gacc[k] += 2.f * dot3(df, dt[k]);
                }
                a = b; b = c; c = d;
#pragma unroll
                for (int k = 0; k < 4; k++) { at[k] = bt[k]; bt[k] = ct[k]; ct[k] = dt[k]; }
            }
        }
    }

    float ivd = d_invden;
#pragma unroll
    for (int k = 0; k < 4; k++) d_g[k * NRES + j] = gacc[k] * ivd;

    // deterministic fixed-order block reduction (double)
    __shared__ double sh[TPB];
    sh[tid] = (double)loss;
    __syncthreads();
    for (int o = TPB / 2; o > 0; o >>= 1) {
        if (tid < o) sh[tid] += sh[tid + o];
        __syncthreads();
    }

    __shared__ bool amLast;
    if (tid == 0) {
        d_part[blockIdx.x] = sh[0];
        __threadfence();
        int t = atomicAdd(&d_ticket, 1);
        amLast = (t == NBLK - 1);
    }
    __syncthreads();
    if (!amLast) return;

    // last block: deterministic fixed-order global reduction + control update
    double s = 0.0;
    for (int q = tid; q < NBLK; q += TPB) s += d_part[q];
    sh[tid] = s;
    __syncthreads();
    for (int o = TPB / 2; o > 0; o >>= 1) {
        if (tid < o) sh[tid] += sh[tid + o];
        __syncthreads();
    }
    if (tid == 0) {
        d_ticket = 0;
        float mse = (float)(sh[0] / (3.0 * (double)d_cnt));
        if (first) {
            if (fabsf(mse - 100.0f) < 1e-4f) d_done = 1;
        } else {
            if (fabsf(mse - d_mse_prev) < 1e-4f) d_done = 1;
            int t1 = d_t + 1; d_t = t1;
            if (t1 >= 200) d_done = 1;
        }
        d_mse_prev = mse;
        float tf = (float)(d_t + 1);
        d_bc1m = 1.0f - powf(0.9f, tf);
        d_bc2v = 1.0f - powf(0.999f, tf);
    }
}

__global__ void k_final(const float* __restrict__ X, float* __restrict__ out) {
    int i = blockIdx.x * TPB + threadIdx.x;
    int j = d_inv[i];
    const float cA = cosf(1.937f), sA = sinf(1.937f);
    const float* xr = X + (size_t)i * 42;
    float* o = out + (size_t)i * 42;
#pragma unroll
    for (int q = 0; q < 12; q++) o[q] = xr[q];   // backbone passthrough

    float chi[4];
#pragma unroll
    for (int k = 0; k < 4; k++) chi[k] = d_chi[k * NRES + j];

    V3 p1 = ldpre(0, j), cb = ldpre(1, j), u1 = ldpre(2, j), n1 = ldpre(3, j), m1 = ldpre(4, j);
    V3 atoms[10];
    atoms[0] = cb;
    float c0 = cosf(chi[0]), s0 = sinf(chi[0]);
    V3 A5 = cb + (u1 * (-cA) + (m1 * c0 + n1 * s0) * sA) * BLEN;
    atoms[1] = A5;
    V3 a = p1, b = cb, c = A5;
#pragma unroll
    for (int s = 2; s < 10; s++) {
        float cT, sT;
        if (s <= 4) { float T = chi[s - 1]; cT = cosf(T); sT = sinf(T); }
        else        { cT = cosf(PI_F); sT = sinf(PI_F); }
        V3 d = extendp(a, b, c, cT, sT);
        atoms[s] = d;
        a = b; b = c; c = d;
    }
#pragma unroll
    for (int s = 0; s < 10; s++) {
        o[12 + 3 * s] = atoms[s].x;
        o[13 + 3 * s] = atoms[s].y;
        o[14 + 3 * s] = atoms[s].z;
    }
}

// ---------------- launch ----------------
extern "C" void kernel_launch(void* const* d_in, const int* in_sizes, int n_in,
                              void* d_out, int out_size) {
    const float* X = (const float*)d_in[0];
    const int*   S = (const int*)d_in[1];
    // d_in[2] = batch_ids: contiguous equal segments -> pure reshape, unused.
    float* out = (float*)d_out;

    k_hist<<<NBLK, TPB>>>(S);
    k_scan<<<1, 32>>>();
    k_scatter<<<NBLK, TPB>>>(X, S);

    // initial loss/gradient at chi0 (no Adam step)
    k_iter<<<NBLK, TPB>>>(0, 1);

    // up to 200 Adam steps, device-side convergence gating, fused reduction
    for (int it = 0; it < 200; ++it)
        k_iter<<<NBLK, TPB>>>(1, 0);

    k_final<<<NBLK, TPB>>>(X, out);
}

// round 3
// speedup vs baseline: 2.0776x; 1.1536x over previous
#include <cuda_runtime.h>
#include <math.h>

// Problem dims (fixed by reference: B=1024, L=256)
#define NRES   262144
#define TPB    256
#define NBLK   (NRES / TPB)    // 1024
#define NCHUNK (NRES / 128)    // 2048 chunks of 128 residues (2 threads each)
#define PGRID  592             // 148 SMs * 4 CTAs -> all resident (launch_bounds enforced)
#define BLEN   1.52f
#define PI_F   3.14159265358979323846f

// ---------------- small vec helpers ----------------
struct V3 { float x, y, z; };
__device__ __forceinline__ V3 v3(float a, float b, float c) { V3 r; r.x = a; r.y = b; r.z = c; return r; }
__device__ __forceinline__ V3 operator+(V3 a, V3 b) { return v3(a.x + b.x, a.y + b.y, a.z + b.z); }
__device__ __forceinline__ V3 operator-(V3 a, V3 b) { return v3(a.x - b.x, a.y - b.y, a.z - b.z); }
__device__ __forceinline__ V3 operator*(V3 a, float s) { return v3(a.x * s, a.y * s, a.z * s); }
__device__ __forceinline__ float dot3(V3 a, V3 b) { return a.x * b.x + a.y * b.y + a.z * b.z; }
__device__ __forceinline__ V3 crs3(V3 a, V3 b) {
    return v3(a.y * b.z - a.z * b.y, a.z * b.x - a.x * b.z, a.x * b.y - a.y * b.x);
}

// ---------------- residue-type tables ----------------
__constant__ int c_nsc[21]  = {1,7,4,4,2,5,5,0,6,4,4,5,4,7,3,2,3,10,8,3,0};
__constant__ int c_chin[21] = {0,4,2,2,1,3,3,0,2,2,2,4,3,2,2,1,1,2,2,1,0};

// ---------------- device state (static; no runtime alloc) ----------------
// Per-residue arrays indexed by SORTED position j (sorted by n_sc).
__device__ float  d_chi[4 * NRES];
__device__ float  d_m  [4 * NRES];
__device__ float  d_v  [4 * NRES];
__device__ float  d_g  [4 * NRES];
__device__ float  d_pre[15 * NRES];   // SoA: p1, CB, u1, n1, m1
__device__ float  d_tgt[30 * NRES];   // SoA transposed sidechain targets
__device__ int    d_nsc[NRES];
__device__ int    d_inv[NRES];        // original i -> sorted j
__device__ int    d_bhist[11 * NBLK];
__device__ double d_part[NCHUNK];
__device__ float  d_mse_prev;
__device__ int    d_done, d_t, d_cnt, d_ticket, d_gen;
__device__ float  d_invden, d_bc1m, d_bc2v;

__device__ __forceinline__ V3 ldpre(int c, int j) {
    return v3(d_pre[(3 * c + 0) * NRES + j], d_pre[(3 * c + 1) * NRES + j], d_pre[(3 * c + 2) * NRES + j]);
}
__device__ __forceinline__ void stpre(int c, int j, V3 a) {
    d_pre[(3 * c + 0) * NRES + j] = a.x;
    d_pre[(3 * c + 1) * NRES + j] = a.y;
    d_pre[(3 * c + 2) * NRES + j] = a.z;
}
__device__ __forceinline__ V3 ldtgt(int s, int j) {
    return v3(d_tgt[(3 * s + 0) * NRES + j], d_tgt[(3 * s + 1) * NRES + j], d_tgt[(3 * s + 2) * NRES + j]);
}

// NeRF extend, primal only
__device__ __forceinline__ V3 extendp(V3 a, V3 b, V3 c, float cT, float sT) {
    const float cA = cosf(1.937f), sA = sinf(1.937f);
    V3 v = c - b; float nv = sqrtf(dot3(v, v)); V3 u = v * (1.f / (nv + 1e-8f));
    V3 w = b - a; V3 pp = crs3(w, u); float np = sqrtf(dot3(pp, pp)); V3 nn = pp * (1.f / (np + 1e-8f));
    V3 mm = crs3(nn, u);
    return c + (u * (-cA) + (mm * cT + nn * sT) * sA) * BLEN;
}

__device__ __forceinline__ float dihed(V3 a, V3 b, V3 c, V3 d) {
    V3 b1 = b - a, b2 = c - b, b3 = d - c;
    V3 n1 = crs3(b1, b2), n2 = crs3(b2, b3);
    float nb = sqrtf(dot3(b2, b2));
    V3 u2 = b2 * (1.f / (nb + 1e-8f));
    V3 m1 = crs3(n1, u2);
    return atan2f(dot3(m1, n2), dot3(n1, n2));
}

// ---------------- counting sort by n_sc (deterministic / stable) ----------------
__global__ void k_hist(const int* __restrict__ S) {
    __shared__ int h[11];
    int tid = threadIdx.x;
    if (tid < 11) h[tid] = 0;
    __syncthreads();
    int i = blockIdx.x * TPB + tid;
    int nsc = c_nsc[S[i] % 21];
    atomicAdd(&h[nsc], 1);
    __syncthreads();
    if (tid < 11) d_bhist[tid * NBLK + blockIdx.x] = h[tid];
}

__global__ void k_scan() {
    int v = threadIdx.x;
    __shared__ int tot[11], base[11];
    if (v < 11) {
        int s = 0;
        for (int b = 0; b < NBLK; b++) s += d_bhist[v * NBLK + b];
        tot[v] = s;
    }
    __syncthreads();
    if (v == 0) {
        int o = 0, cnt = 0;
        for (int u = 0; u < 11; u++) { base[u] = o; o += tot[u]; cnt += u * tot[u]; }
        d_cnt = cnt;
        d_invden = 1.0f / (3.0f * (float)cnt);
        d_done = 0; d_t = 0; d_mse_prev = 100.0f; d_ticket = 0; d_gen = 0;
        d_bc1m = 1.0f - powf(0.9f, 1.0f);
        d_bc2v = 1.0f - powf(0.999f, 1.0f);
    }
    __syncthreads();
    if (v < 11) {
        int off = base[v];
        for (int b = 0; b < NBLK; b++) {
            int t = d_bhist[v * NBLK + b];
            d_bhist[v * NBLK + b] = off;
            off += t;
        }
    }
}

// scatter + per-residue precompute, stored at sorted position j
__global__ void k_scatter(const float* __restrict__ X, const int* __restrict__ S) {
    int tid = threadIdx.x;
    int i = blockIdx.x * TPB + tid;
    int w = tid >> 5, lane = tid & 31;

    int s20 = S[i] % 21;
    int nsc = c_nsc[s20], chin = c_chin[s20];

    __shared__ int whist[8][11];
    if (tid < 88) ((int*)whist)[tid] = 0;
    __syncthreads();
    unsigned mmask = __match_any_sync(0xffffffffu, nsc);
    int rank = __popc(mmask & ((1u << lane) - 1u));
    if (rank == 0) whist[w][nsc] = __popc(mmask);
    __syncthreads();
    int wb = 0;
    for (int w2 = 0; w2 < w; w2++) wb += whist[w2][nsc];
    int j = d_bhist[nsc * NBLK + blockIdx.x] + wb + rank;

    d_inv[i] = j;
    d_nsc[j] = nsc;

    const float* xr = X + (size_t)i * 42;
    V3 p[9];
#pragma unroll
    for (int q = 0; q < 9; q++) p[q] = v3(xr[3 * q], xr[3 * q + 1], xr[3 * q + 2]);

    const int Q[4][4] = {{0,1,4,5},{1,4,5,6},{4,5,6,7},{5,6,7,8}};
#pragma unroll
    for (int k = 0; k < 4; k++) {
        float ch = 0.f;
        if (k < chin) ch = dihed(p[Q[k][0]], p[Q[k][1]], p[Q[k][2]], p[Q[k][3]]);
        d_chi[k * NRES + j] = ch;
        d_m[k * NRES + j] = 0.f;
        d_v[k * NRES + j] = 0.f;
    }

    V3 cb = extendp(p[0], p[2], p[1], cosf(-2.14f), sinf(-2.14f));
    V3 vv = cb - p[1]; float nv = sqrtf(dot3(vv, vv)); V3 u = vv * (1.f / (nv + 1e-8f));
    V3 ww = p[1] - p[0]; V3 pp = crs3(ww, u); float np = sqrtf(dot3(pp, pp)); V3 nn = pp * (1.f / (np + 1e-8f));
    V3 mm = crs3(nn, u);
    stpre(0, j, p[1]); stpre(1, j, cb); stpre(2, j, u); stpre(3, j, nn); stpre(4, j, mm);

#pragma unroll
    for (int s = 0; s < 10; s++) {
#pragma unroll
        for (int q = 0; q < 3; q++) d_tgt[(3 * s + q) * NRES + j] = xr[(4 + s) * 3 + q];
    }
}

// ---------------- persistent optimizer: 200 Adam iterations in one kernel ----------------
// 2 threads per residue (2 JVP tangents each). Static chunk->block mapping keeps
// per-residue state L1-coherent. Software grid barrier (ticket + generation).
__global__ void __launch_bounds__(TPB, 4) k_opt() {
    const int tid  = threadIdx.x;
    const int lane = tid & 31;
    const int wrp  = tid >> 5;
    const int half = tid & 1;
    const float cA = cosf(1.937f), sA = sinf(1.937f);
    const float COS_PI = cosf(PI_F), SIN_PI = sinf(PI_F);
    const float ivd = d_invden;

    __shared__ double wsum[8];
    __shared__ int s_win;

    for (int it = 0; it <= 200; ++it) {
        if (*(volatile int*)&d_done) break;
        const float b1c = *(volatile float*)&d_bc1m;
        const float b2c = *(volatile float*)&d_bc2v;
        const bool step = (it > 0);

        for (int cch = blockIdx.x; cch < NCHUNK; cch += PGRID) {
            const int r = (cch << 7) + (tid >> 1);

            // ---- chi: this thread owns chis {2*half, 2*half+1} ----
            float myc0, myc1;
            {
                const int k0 = half * 2;
                if (step) {
#pragma unroll
                    for (int q = 0; q < 2; q++) {
                        const int idx = (k0 + q) * NRES + r;
                        float g = d_g[idx];
                        float m = 0.9f * d_m[idx] + 0.1f * g;
                        float v = 0.999f * d_v[idx] + 0.001f * g * g;
                        d_m[idx] = m; d_v[idx] = v;
                        float mh = m / b1c, vh = v / b2c;
                        float cc = d_chi[idx] - mh / (sqrtf(vh) + 1e-8f);
                        d_chi[idx] = cc;
                        if (q == 0) myc0 = cc; else myc1 = cc;
                    }
                } else {
                    myc0 = d_chi[k0 * NRES + r];
                    myc1 = d_chi[(k0 + 1) * NRES + r];
                }
            }
            const float oc0 = __shfl_xor_sync(0xffffffffu, myc0, 1);
            const float oc1 = __shfl_xor_sync(0xffffffffu, myc1, 1);
            float chi[4];
            chi[half * 2]           = myc0;
            chi[half * 2 + 1]       = myc1;
            chi[(1 - half) * 2]     = oc0;
            chi[(1 - half) * 2 + 1] = oc1;

            const int nsc = d_nsc[r];
            const unsigned nscmax = __reduce_max_sync(0xffffffffu, (unsigned)nsc);

            float loss = 0.f, g0 = 0.f, g1 = 0.f;

            if (nscmax > 0) {
                V3 cb = ldpre(1, r);
                if (nsc > 0) { V3 df = cb - ldtgt(0, r); loss += dot3(df, df); }

                if (nscmax > 1) {
                    V3 p1 = ldpre(0, r), u1 = ldpre(2, r), n1 = ldpre(3, r), m1 = ldpre(4, r);
                    float s0, c0; sincosf(chi[0], &s0, &c0);
                    V3 A5 = cb + (u1 * (-cA) + (m1 * c0 + n1 * s0) * sA) * BLEN;
                    V3 t5 = (n1 * c0 - m1 * s0) * (sA * BLEN);
                    if (nsc > 1) {
                        V3 df = A5 - ldtgt(1, r);
                        loss += dot3(df, df);
                        if (half == 0) g0 += 2.f * dot3(df, t5);
                    }

                    V3 a = p1, b = cb, c = A5;
                    V3 at[2], bt[2], ct[2];
#pragma unroll
                    for (int q = 0; q < 2; q++) { at[q] = v3(0,0,0); bt[q] = v3(0,0,0); ct[q] = v3(0,0,0); }
                    if (half == 0) ct[0] = t5;

#pragma unroll
                    for (int s = 2; s < 10; s++) {
                        if ((unsigned)s >= nscmax) break;   // warp-uniform after sort
                        float cT, sT; int ka;
                        if (s <= 4) { sincosf(chi[s - 1], &sT, &cT); ka = s - 1; }
                        else        { cT = COS_PI; sT = SIN_PI; ka = -1; }

                        V3 v = c - b;
                        float nv = sqrtf(dot3(v, v));
                        float iv = 1.f / (nv + 1e-8f);
                        float rnv = 1.f / nv;
                        V3 u = v * iv;
                        V3 w = b - a;
                        V3 pp = crs3(w, u);
                        float np = sqrtf(dot3(pp, pp));
                        float ip = 1.f / (np + 1e-8f);
                        float rnp = 1.f / np;
                        V3 nn = pp * ip;
                        V3 mm = crs3(nn, u);
                        V3 d = c + (u * (-cA) + (mm * cT + nn * sT) * sA) * BLEN;

                        V3 dt[2];
#pragma unroll
                        for (int q = 0; q < 2; q++) {
                            V3 vd = ct[q] - bt[q];
                            float nvd = dot3(v, vd) * rnv;
                            V3 ud = vd * iv - v * (nvd * iv * iv);
                            V3 wd = bt[q] - at[q];
                            V3 pd = crs3(wd, u) + crs3(w, ud);
                            float npd = dot3(pp, pd) * rnp;
                            V3 nd = pd * ip - pp * (npd * ip * ip);
                            V3 md = crs3(nd, u) + crs3(nn, ud);
                            V3 dd = ct[q] + (ud * (-cA) + (md * cT + nd * sT) * sA) * BLEN;
                            if (half * 2 + q == ka) dd = dd + (nn * cT - mm * sT) * (sA * BLEN);
                            dt[q] = dd;
                        }

                        if (s < nsc) {
                            V3 df = d - ldtgt(s, r);
                            loss += dot3(df, df);
                            g0 += 2.f * dot3(df, dt[0]);
                            g1 += 2.f * dot3(df, dt[1]);
                        }
                        a = b; b = c; c = d;
#pragma unroll
                        for (int q = 0; q < 2; q++) { at[q] = bt[q]; bt[q] = ct[q]; ct[q] = dt[q]; }
                    }
                }
            }

            d_g[(half * 2 + 0) * NRES + r] = g0 * ivd;
            d_g[(half * 2 + 1) * NRES + r] = g1 * ivd;

            // per-chunk loss reduction (both threads hold identical primal loss -> x0.5 exact)
            double val = (double)loss;
#pragma unroll
            for (int o = 16; o; o >>= 1) val += __shfl_down_sync(0xffffffffu, val, o);
            if (lane == 0) wsum[wrp] = val;
            __syncthreads();
            if (tid == 0) {
                double s2 = 0.0;
#pragma unroll
                for (int q2 = 0; q2 < 8; q2++) s2 += wsum[q2];
                d_part[cch] = s2 * 0.5;
            }
            __syncthreads();
        }

        // ---- grid barrier: ticket + last-block global reduce + generation release ----
        if (tid == 0) {
            __threadfence();
            int t = atomicAdd(&d_ticket, 1);
            s_win = (t == PGRID - 1);
        }
        __syncthreads();
        if (s_win) {
            __threadfence();   // acquire: all partials visible
            double s = 0.0;
            for (int q = tid; q < NCHUNK; q += TPB) s += *((volatile double*)&d_part[q]);
#pragma unroll
            for (int o = 16; o; o >>= 1) s += __shfl_down_sync(0xffffffffu, s, o);
            if (lane == 0) wsum[wrp] = s;
            __syncthreads();
            if (tid == 0) {
                double tot = 0.0;
#pragma unroll
                for (int q2 = 0; q2 < 8; q2++) tot += wsum[q2];
                float mse = (float)(tot / (3.0 * (double)d_cnt));
                if (it == 0) {
                    if (fabsf(mse - 100.0f) < 1e-4f) d_done = 1;
                } else {
                    if (fabsf(mse - d_mse_prev) < 1e-4f) d_done = 1;
                    int t1 = d_t + 1; d_t = t1;
                    if (t1 >= 200) d_done = 1;
                }
                d_mse_prev = mse;
                float tf = (float)(d_t + 1);
                d_bc1m = 1.0f - powf(0.9f, tf);
                d_bc2v = 1.0f - powf(0.999f, tf);
                atomicExch(&d_ticket, 0);
                __threadfence();
                atomicExch(&d_gen, it + 1);
            }
            __syncthreads();
        }
        if (tid == 0) {
            while (atomicAdd(&d_gen, 0) <= it) __nanosleep(64);
        }
        __syncthreads();
        __threadfence();
    }
}

__global__ void k_final(const float* __restrict__ X, float* __restrict__ out) {
    int i = blockIdx.x * TPB + threadIdx.x;
    int j = d_inv[i];
    const float cA = cosf(1.937f), sA = sinf(1.937f);
    const float* xr = X + (size_t)i * 42;
    float* o = out + (size_t)i * 42;
#pragma unroll
    for (int q = 0; q < 12; q++) o[q] = xr[q];   // backbone passthrough

    float chi[4];
#pragma unroll
    for (int k = 0; k < 4; k++) chi[k] = d_chi[k * NRES + j];

    V3 p1 = ldpre(0, j), cb = ldpre(1, j), u1 = ldpre(2, j), n1 = ldpre(3, j), m1 = ldpre(4, j);
    V3 atoms[10];
    atoms[0] = cb;
    float c0 = cosf(chi[0]), s0 = sinf(chi[0]);
    V3 A5 = cb + (u1 * (-cA) + (m1 * c0 + n1 * s0) * sA) * BLEN;
    atoms[1] = A5;
    V3 a = p1, b = cb, c = A5;
#pragma unroll
    for (int s = 2; s < 10; s++) {
        float cT, sT;
        if (s <= 4) { float T = chi[s - 1]; cT = cosf(T); sT = sinf(T); }
        else        { cT = cosf(PI_F); sT = sinf(PI_F); }
        V3 d = extendp(a, b, c, cT, sT);
        atoms[s] = d;
        a = b; b = c; c = d;
    }
#pragma unroll
    for (int s = 0; s < 10; s++) {
        o[12 + 3 * s] = atoms[s].x;
        o[13 + 3 * s] = atoms[s].y;
        o[14 + 3 * s] = atoms[s].z;
    }
}

// ---------------- launch ----------------
extern "C" void kernel_launch(void* const* d_in, const int* in_sizes, int n_in,
                              void* d_out, int out_size) {
    const float* X = (const float*)d_in[0];
    const int*   S = (const int*)d_in[1];
    // d_in[2] = batch_ids: contiguous equal segments -> pure reshape, unused.
    float* out = (float*)d_out;

    k_hist<<<NBLK, TPB>>>(S);
    k_scan<<<1, 32>>>();
    k_scatter<<<NBLK, TPB>>>(X, S);
    k_opt<<<PGRID, TPB>>>();
    k_final<<<NBLK, TPB>>>(X, out);
}